// round 10
// baseline (speedup 1.0000x reference)
#include <cuda_runtime.h>
#include <cuda_bf16.h>
#include <cstdint>

// ---------------------------------------------------------------------------
// FixedTopKLoRALinear: out = x@W^T + bias + softtopk(x@A^T)@B^T
// Shapes fixed: x[8192,4096], A[64,4096], B[4096,64], W[4096,4096], bias[4096]
// Strategy: tf32 mma.sync (m16n8k8) — the tcgen05 path does NOT assemble under
// this harness (ptxas targets plain sm_103, rejects tcgen05.*).
// Operands pre-converted to tf32 bits in gmem (removes CVT from hot loop);
// 256 threads (2 warps/SMSP for latency hiding); BK=64; LoRA fused as one
// extra K-block (R=64).
// ---------------------------------------------------------------------------

#define D_IN_C   4096
#define N_FIX    4096
#define R_C      64
#define KSEL_C   16
#define TEMP_C   0.1f
#define MAX_M    8192

// Scratch (allocation-free: device globals)
__device__ uint32_t g_xt[MAX_M * D_IN_C];   // x   as tf32 bits
__device__ uint32_t g_wt[N_FIX * D_IN_C];   // W   as tf32 bits
__device__ uint32_t g_at[R_C  * D_IN_C];    // A   as tf32 bits
__device__ uint32_t g_bt[N_FIX * R_C];      // B   as tf32 bits
__device__ float    g_z  [MAX_M * R_C];
__device__ uint32_t g_zst[MAX_M * R_C];     // z_sparse as tf32 bits

// ---------------------------------------------------------------------------
__device__ __forceinline__ uint32_t f2tf32(float f) {
    uint32_t r;
    asm("cvt.rna.tf32.f32 %0, %1;" : "=r"(r) : "f"(f));
    return r;
}

__device__ __forceinline__ void mma_tf32(float* d, const uint32_t* a, const uint32_t* b) {
    asm volatile(
        "mma.sync.aligned.m16n8k8.row.col.f32.tf32.tf32.f32 "
        "{%0,%1,%2,%3},{%4,%5,%6,%7},{%8,%9},{%0,%1,%2,%3};"
        : "+f"(d[0]), "+f"(d[1]), "+f"(d[2]), "+f"(d[3])
        : "r"(a[0]), "r"(a[1]), "r"(a[2]), "r"(a[3]), "r"(b[0]), "r"(b[1]));
}

__device__ __forceinline__ void cp_async16(uint32_t* dst_smem, const uint32_t* src_gmem) {
    uint32_t s = (uint32_t)__cvta_generic_to_shared(dst_smem);
    asm volatile("cp.async.cg.shared.global [%0], [%1], 16;\n" :: "r"(s), "l"(src_gmem));
}

// ---------------------------------------------------------------------------
// GEMM: out[m][n] = sum_k X[m][k] * Wt[n][k]  (tf32 bits in, fp32 out)
// BM=128, BK=64, 256 threads = 8 warps as 2(m) x 4(n).
// Warp tile 64 x (BN/4); m16n8k8 tiles: MT=4, NT=BN/32.
// Pitch 68 (== 4 mod 32): quad-pattern fragment LDS hits 32 distinct banks.
// ---------------------------------------------------------------------------
#define BM_G    128
#define BK_G    64
#define PITCH_G 68

template<int BN, bool FUSE_LORA, bool ADD_BIAS>
__global__ void __launch_bounds__(256)
gemm_tf32p(const uint32_t* __restrict__ X,  int ldx,
           const uint32_t* __restrict__ Wt, int ldw,
           const uint32_t* __restrict__ ZS,   // [M][R_C] tf32 (FUSE only)
           const uint32_t* __restrict__ BL,   // [N][R_C] tf32 (FUSE only)
           const float* __restrict__ bias,
           float* __restrict__ out, int ldo,
           int KT_main, int KT_total)
{
    constexpr int NT = BN / 32;                // n8 tiles per warp
    extern __shared__ uint32_t smem[];
    uint32_t* As = smem;                       // [2][BM_G][PITCH_G]
    uint32_t* Bs = smem + 2 * BM_G * PITCH_G;  // [2][BN][PITCH_G]

    const int tid  = threadIdx.x;
    const int lane = tid & 31;
    const int wid  = tid >> 5;
    const int wm   = wid >> 2;     // 0..1 -> m offset 64
    const int wn   = wid & 3;      // 0..3 -> n offset BN/4

    const int bm = blockIdx.y * BM_G;
    const int bn = blockIdx.x * BN;

    float acc[4][NT][4];
#pragma unroll
    for (int mt = 0; mt < 4; mt++)
#pragma unroll
        for (int nt = 0; nt < NT; nt++)
#pragma unroll
            for (int i = 0; i < 4; i++) acc[mt][nt][i] = 0.0f;

    auto issue_copy = [&](int kb, int stage) {
        uint32_t* as = As + stage * BM_G * PITCH_G;
        uint32_t* bs = Bs + stage * BN * PITCH_G;
        const bool main_k = (!FUSE_LORA) || (kb < KT_main);
        // A tile: BM_G x BK_G -> 2048 uint4, 256 threads -> 8 iters
#pragma unroll
        for (int i = 0; i < (BM_G * BK_G) / (4 * 256); i++) {
            int linear = tid + i * 256;
            int row = linear >> 4;             // 16 uint4 per 64-elem row
            int cv  = (linear & 15) << 2;
            const uint32_t* src = main_k
                ? X  + (size_t)(bm + row) * ldx + (size_t)kb * BK_G + cv
                : ZS + (size_t)(bm + row) * R_C + cv;
            cp_async16(&as[row * PITCH_G + cv], src);
        }
        // B tile: BN x BK_G
#pragma unroll
        for (int i = 0; i < (BN * BK_G) / (4 * 256); i++) {
            int linear = tid + i * 256;
            int row = linear >> 4;
            int cv  = (linear & 15) << 2;
            const uint32_t* src = main_k
                ? Wt + (size_t)(bn + row) * ldw + (size_t)kb * BK_G + cv
                : BL + (size_t)(bn + row) * R_C + cv;
            cp_async16(&bs[row * PITCH_G + cv], src);
        }
        asm volatile("cp.async.commit_group;\n" ::: "memory");
    };

    issue_copy(0, 0);

    for (int kb = 0; kb < KT_total; kb++) {
        const int stage = kb & 1;
        if (kb + 1 < KT_total) {
            issue_copy(kb + 1, (kb + 1) & 1);
            asm volatile("cp.async.wait_group 1;\n" ::: "memory");
        } else {
            asm volatile("cp.async.wait_group 0;\n" ::: "memory");
        }
        __syncthreads();

        const uint32_t* as = As + stage * BM_G * PITCH_G + (wm * 64) * PITCH_G;
        const uint32_t* bs = Bs + stage * BN * PITCH_G + (wn * (BN / 4)) * PITCH_G;

#pragma unroll
        for (int kk = 0; kk < BK_G / 8; kk++) {
            uint32_t afrag[4][4];
#pragma unroll
            for (int mt = 0; mt < 4; mt++) {
                int r = mt * 16 + (lane >> 2);
                int c = kk * 8 + (lane & 3);
                afrag[mt][0] = as[r * PITCH_G + c];
                afrag[mt][1] = as[(r + 8) * PITCH_G + c];
                afrag[mt][2] = as[r * PITCH_G + c + 4];
                afrag[mt][3] = as[(r + 8) * PITCH_G + c + 4];
            }
            uint32_t bfrag[NT][2];
#pragma unroll
            for (int nt = 0; nt < NT; nt++) {
                int n = nt * 8 + (lane >> 2);
                int c = kk * 8 + (lane & 3);
                bfrag[nt][0] = bs[n * PITCH_G + c];
                bfrag[nt][1] = bs[n * PITCH_G + c + 4];
            }
#pragma unroll
            for (int mt = 0; mt < 4; mt++)
#pragma unroll
                for (int nt = 0; nt < NT; nt++)
                    mma_tf32(acc[mt][nt], afrag[mt], bfrag[nt]);
        }
        __syncthreads();
    }

    // Epilogue
#pragma unroll
    for (int mt = 0; mt < 4; mt++) {
#pragma unroll
        for (int nt = 0; nt < NT; nt++) {
            int r0 = bm + wm * 64 + mt * 16 + (lane >> 2);
            int c0 = bn + wn * (BN / 4) + nt * 8 + (lane & 3) * 2;
            float b0 = 0.0f, b1 = 0.0f;
            if (ADD_BIAS) { b0 = __ldg(&bias[c0]); b1 = __ldg(&bias[c0 + 1]); }
            float2 v0 = make_float2(acc[mt][nt][0] + b0, acc[mt][nt][1] + b1);
            float2 v1 = make_float2(acc[mt][nt][2] + b0, acc[mt][nt][3] + b1);
            *(float2*)&out[(size_t)r0 * ldo + c0]       = v0;
            *(float2*)&out[(size_t)(r0 + 8) * ldo + c0] = v1;
        }
    }
}

// ---------------------------------------------------------------------------
// fp32 -> tf32-bits conversion (rna), vectorized grid-stride
// ---------------------------------------------------------------------------
__global__ void cvt_tf32_kernel(const float4* __restrict__ in,
                                uint4* __restrict__ out, int n4)
{
    int i = blockIdx.x * blockDim.x + threadIdx.x;
    const int stride = gridDim.x * blockDim.x;
    for (; i < n4; i += stride) {
        float4 v = in[i];
        uint4 o;
        o.x = f2tf32(v.x); o.y = f2tf32(v.y);
        o.z = f2tf32(v.z); o.w = f2tf32(v.w);
        out[i] = o;
    }
}

// ---------------------------------------------------------------------------
// Soft top-k mask: one warp per row of 64 z values.  Exact 16th-largest |z|
// (duplicate-counting) via 16 max-extractions; emit z_sparse as tf32 bits.
// ---------------------------------------------------------------------------
__global__ void topk_mask_kernel(const float* __restrict__ z,
                                 uint32_t* __restrict__ zst, int M)
{
    const int row  = blockIdx.x * 8 + (threadIdx.x >> 5);
    const int lane = threadIdx.x & 31;
    if (row >= M) return;

    float z0 = z[row * R_C + lane];
    float z1 = z[row * R_C + lane + 32];
    float v0 = fabsf(z0), v1 = fabsf(z1);
    bool a0 = true, a1 = true;
    float thr = 0.0f;

#pragma unroll 1
    for (int it = 0; it < KSEL_C; it++) {
        float m = fmaxf(a0 ? v0 : -1.0f, a1 ? v1 : -1.0f);
#pragma unroll
        for (int off = 16; off; off >>= 1)
            m = fmaxf(m, __shfl_xor_sync(0xffffffffu, m, off));
        thr = m;
        unsigned b = __ballot_sync(0xffffffffu, a0 && v0 == m);
        if (b) {
            if (lane == (__ffs(b) - 1)) a0 = false;
        } else {
            unsigned b2 = __ballot_sync(0xffffffffu, a1 && v1 == m);
            if (lane == (__ffs(b2) - 1)) a1 = false;
        }
    }

    const float inv_t = 1.0f / TEMP_C;
    float m0 = 1.0f / (1.0f + expf(-(v0 - thr) * inv_t));
    float m1 = 1.0f / (1.0f + expf(-(v1 - thr) * inv_t));
    zst[row * R_C + lane]      = f2tf32(z0 * m0);
    zst[row * R_C + lane + 32] = f2tf32(z1 * m1);
}

// ---------------------------------------------------------------------------
// Launch
// ---------------------------------------------------------------------------
extern "C" void kernel_launch(void* const* d_in, const int* in_sizes, int n_in,
                              void* d_out, int out_size)
{
    const float* x    = (const float*)d_in[0];   // [M][4096]
    const float* Amat = (const float*)d_in[1];   // [64][4096]
    const float* Bmat = (const float*)d_in[2];   // [4096][64]
    const float* Wmat = (const float*)d_in[3];   // [4096][4096]
    const float* bias = (const float*)d_in[4];   // [4096]
    float* out = (float*)d_out;

    const int M = in_sizes[0] / D_IN_C;          // 8192
    const int N = in_sizes[4];                   // 4096

    uint32_t *xt, *wt, *at, *bt, *zst;
    float* zptr;
    cudaGetSymbolAddress((void**)&xt,   g_xt);
    cudaGetSymbolAddress((void**)&wt,   g_wt);
    cudaGetSymbolAddress((void**)&at,   g_at);
    cudaGetSymbolAddress((void**)&bt,   g_bt);
    cudaGetSymbolAddress((void**)&zst,  g_zst);
    cudaGetSymbolAddress((void**)&zptr, g_z);

    // 0) pre-convert operands to tf32 bits (removes CVT from GEMM hot loops)
    cvt_tf32_kernel<<<1024, 256>>>((const float4*)x,    (uint4*)xt, M * D_IN_C / 4);
    cvt_tf32_kernel<<<1024, 256>>>((const float4*)Wmat, (uint4*)wt, N * D_IN_C / 4);
    cvt_tf32_kernel<<<256,  256>>>((const float4*)Amat, (uint4*)at, R_C * D_IN_C / 4);
    cvt_tf32_kernel<<<256,  256>>>((const float4*)Bmat, (uint4*)bt, N * R_C / 4);

    constexpr int SMEM_MAIN = 2 * (BM_G + 128) * PITCH_G * 4;  // 139264 B
    constexpr int SMEM_Z    = 2 * (BM_G + 64)  * PITCH_G * 4;  // 104448 B
    cudaFuncSetAttribute(gemm_tf32p<128, true,  true>,
                         cudaFuncAttributeMaxDynamicSharedMemorySize, SMEM_MAIN);
    cudaFuncSetAttribute(gemm_tf32p<64,  false, false>,
                         cudaFuncAttributeMaxDynamicSharedMemorySize, SMEM_Z);

    // 1) z = x @ A^T   (M x 64, K = 4096)
    {
        dim3 grid(64 / 64, M / BM_G);
        gemm_tf32p<64, false, false><<<grid, 256, SMEM_Z>>>(
            xt, D_IN_C, at, D_IN_C,
            nullptr, nullptr, nullptr,
            zptr, R_C,
            D_IN_C / BK_G, D_IN_C / BK_G);
    }

    // 2) soft top-k mask -> z_sparse (tf32 bits)
    topk_mask_kernel<<<M / 8, 256>>>(zptr, zst, M);

    // 3) out = x @ W^T + bias + z_sparse @ B^T   (LoRA = one extra K-block)
    {
        dim3 grid(N / 128, M / BM_G);
        gemm_tf32p<128, true, true><<<grid, 256, SMEM_MAIN>>>(
            xt, D_IN_C, wt, D_IN_C,
            zst, bt, bias,
            out, N,
            D_IN_C / BK_G, D_IN_C / BK_G + 1);
    }
}

// round 11
// speedup vs baseline: 2.1918x; 2.1918x over previous
#include <cuda_runtime.h>
#include <cuda_fp16.h>
#include <cstdint>

// ---------------------------------------------------------------------------
// FixedTopKLoRALinear: out = x@W^T + bias + softtopk(x@A^T)@B^T
// x[8192,4096], A[64,4096], B[4096,64], W[4096,4096], bias[4096]
//
// fp16 m16n8k16 mma.sync (fp32 accum). fp16 mantissa == tf32 mantissa (10b),
// so rel_err matches the passing tf32 kernel (~3e-4) at 2x FLOP/instruction
// and half the operand bytes. tcgen05 is unavailable (ptxas targets sm_103).
// Smem holds fp16 PAIRS as uint32, pitch 36 words/row (conflict-free quad
// pattern). K-tile = 64 fp16 = 32 pairs -> 64 outer iters (was 128).
// LoRA fused as one extra K-tile (R=64). 2-stage cp.async pipeline.
// ---------------------------------------------------------------------------

#define D_IN_C   4096
#define D_IN_P   2048          // fp16 pairs per x/W/A row
#define N_FIX    4096
#define R_C      64
#define R_P      32            // fp16 pairs per zs/B row
#define KSEL_C   16
#define TEMP_C   0.1f
#define MAX_M    8192

#define PITCH    36            // uint32 words per smem row

// Scratch (allocation-free: device globals)
__device__ uint32_t g_xh [MAX_M * D_IN_P];   // x  as fp16 pairs
__device__ uint32_t g_wh [N_FIX * D_IN_P];   // W  as fp16 pairs
__device__ uint32_t g_ah [R_C   * D_IN_P];   // A  as fp16 pairs
__device__ uint32_t g_bh [N_FIX * R_P];      // B  as fp16 pairs
__device__ float    g_z  [MAX_M * R_C];
__device__ uint32_t g_zsh[MAX_M * R_P];      // z_sparse as fp16 pairs

// ---------------------------------------------------------------------------
__device__ __forceinline__ uint32_t pack2(float a, float b) {
    __half2 h = __floats2half2_rn(a, b);
    return *(uint32_t*)&h;
}

__device__ __forceinline__ void mma_f16(float* d, const uint32_t* a, const uint32_t* b) {
    asm volatile(
        "mma.sync.aligned.m16n8k16.row.col.f32.f16.f16.f32 "
        "{%0,%1,%2,%3},{%4,%5,%6,%7},{%8,%9},{%0,%1,%2,%3};"
        : "+f"(d[0]), "+f"(d[1]), "+f"(d[2]), "+f"(d[3])
        : "r"(a[0]), "r"(a[1]), "r"(a[2]), "r"(a[3]), "r"(b[0]), "r"(b[1]));
}

__device__ __forceinline__ void cp_async16(uint32_t* dst_smem, const uint32_t* src_gmem) {
    uint32_t s = (uint32_t)__cvta_generic_to_shared(dst_smem);
    asm volatile("cp.async.cg.shared.global [%0], [%1], 16;\n" :: "r"(s), "l"(src_gmem));
}

// ---------------------------------------------------------------------------
// fp16 GEMM: out[m][n] = sum_k X[m][k] * Wt[n][k]   (+ LoRA K-tile + bias)
// BM x BN block, 128 threads = 4 warps (2m x 2n), warp tile (BM/2)x(BN/2).
// Smem tiles: [2][BM][PITCH] pairs for A-side, [2][BN][PITCH] for B-side;
// each tile holds 32 pairs (=64 fp16) of K.  4 k16 steps per tile.
// ---------------------------------------------------------------------------
template<int BM, int BN, bool FUSE_LORA, bool ADD_BIAS>
__global__ void __launch_bounds__(128)
gemm_f16(const uint32_t* __restrict__ X,  int ldx,      // pairs
         const uint32_t* __restrict__ Wt, int ldw,      // pairs
         const uint32_t* __restrict__ ZS,   // [M][R_P] pairs (FUSE only)
         const uint32_t* __restrict__ BL,   // [N][R_P] pairs (FUSE only)
         const float* __restrict__ bias,
         float* __restrict__ out, int ldo,
         int KT_main, int KT_total)
{
    constexpr int MT = BM / 32;     // m16 tiles per warp
    constexpr int NT = BN / 16;     // n8  tiles per warp
    extern __shared__ uint32_t smem[];
    uint32_t* As = smem;                    // [2][BM][PITCH]
    uint32_t* Bs = smem + 2 * BM * PITCH;   // [2][BN][PITCH]

    const int tid  = threadIdx.x;
    const int lane = tid & 31;
    const int wid  = tid >> 5;
    const int wm   = wid >> 1;      // 0..1
    const int wn   = wid & 1;       // 0..1

    const int bm = blockIdx.y * BM;
    const int bn = blockIdx.x * BN;

    float acc[MT][NT][4];
#pragma unroll
    for (int mt = 0; mt < MT; mt++)
#pragma unroll
        for (int nt = 0; nt < NT; nt++)
#pragma unroll
            for (int i = 0; i < 4; i++) acc[mt][nt][i] = 0.0f;

    auto issue_copy = [&](int kb, int stage) {
        uint32_t* as = As + stage * BM * PITCH;
        uint32_t* bs = Bs + stage * BN * PITCH;
        const bool main_k = (!FUSE_LORA) || (kb < KT_main);
        // A tile: BM rows x 8 uint4 each
#pragma unroll
        for (int i = 0; i < BM / 16; i++) {
            int linear = tid + i * 128;
            int row = linear >> 3;
            int cv  = (linear & 7) << 2;     // pair index 0..28
            const uint32_t* src = main_k
                ? X  + (size_t)(bm + row) * ldx + (size_t)kb * 32 + cv
                : ZS + (size_t)(bm + row) * R_P + cv;
            cp_async16(&as[row * PITCH + cv], src);
        }
        // B tile: BN rows x 8 uint4 each
#pragma unroll
        for (int i = 0; i < BN / 16; i++) {
            int linear = tid + i * 128;
            int row = linear >> 3;
            int cv  = (linear & 7) << 2;
            const uint32_t* src = main_k
                ? Wt + (size_t)(bn + row) * ldw + (size_t)kb * 32 + cv
                : BL + (size_t)(bn + row) * R_P + cv;
            cp_async16(&bs[row * PITCH + cv], src);
        }
        asm volatile("cp.async.commit_group;\n" ::: "memory");
    };

    issue_copy(0, 0);

    for (int kb = 0; kb < KT_total; kb++) {
        const int stage = kb & 1;
        if (kb + 1 < KT_total) {
            issue_copy(kb + 1, (kb + 1) & 1);
            asm volatile("cp.async.wait_group 1;\n" ::: "memory");
        } else {
            asm volatile("cp.async.wait_group 0;\n" ::: "memory");
        }
        __syncthreads();

        const uint32_t* as = As + stage * BM * PITCH + (wm * (BM / 2)) * PITCH;
        const uint32_t* bs = Bs + stage * BN * PITCH + (wn * (BN / 2)) * PITCH;

        // 4 k16 steps per 64-element K-tile (8 pairs each)
#pragma unroll
        for (int kk = 0; kk < 4; kk++) {
            uint32_t afrag[MT][4];
#pragma unroll
            for (int mt = 0; mt < MT; mt++) {
                int r = mt * 16 + (lane >> 2);
                int c = kk * 8 + (lane & 3);
                afrag[mt][0] = as[r * PITCH + c];
                afrag[mt][1] = as[(r + 8) * PITCH + c];
                afrag[mt][2] = as[r * PITCH + c + 4];
                afrag[mt][3] = as[(r + 8) * PITCH + c + 4];
            }
            uint32_t bfrag[NT][2];
#pragma unroll
            for (int nt = 0; nt < NT; nt++) {
                int n = nt * 8 + (lane >> 2);
                int c = kk * 8 + (lane & 3);
                bfrag[nt][0] = bs[n * PITCH + c];
                bfrag[nt][1] = bs[n * PITCH + c + 4];
            }
#pragma unroll
            for (int mt = 0; mt < MT; mt++)
#pragma unroll
                for (int nt = 0; nt < NT; nt++)
                    mma_f16(acc[mt][nt], afrag[mt], bfrag[nt]);
        }
        __syncthreads();
    }

    // Epilogue
#pragma unroll
    for (int mt = 0; mt < MT; mt++) {
#pragma unroll
        for (int nt = 0; nt < NT; nt++) {
            int r0 = bm + wm * (BM / 2) + mt * 16 + (lane >> 2);
            int c0 = bn + wn * (BN / 2) + nt * 8 + (lane & 3) * 2;
            float b0 = 0.0f, b1 = 0.0f;
            if (ADD_BIAS) { b0 = __ldg(&bias[c0]); b1 = __ldg(&bias[c0 + 1]); }
            float2 v0 = make_float2(acc[mt][nt][0] + b0, acc[mt][nt][1] + b1);
            float2 v1 = make_float2(acc[mt][nt][2] + b0, acc[mt][nt][3] + b1);
            *(float2*)&out[(size_t)r0 * ldo + c0]       = v0;
            *(float2*)&out[(size_t)(r0 + 8) * ldo + c0] = v1;
        }
    }
}

// ---------------------------------------------------------------------------
// fp32 -> fp16-pair conversion (rn), vectorized grid-stride
// ---------------------------------------------------------------------------
__global__ void cvt_f16_kernel(const float4* __restrict__ in,
                               uint2* __restrict__ out, int n4)
{
    int i = blockIdx.x * blockDim.x + threadIdx.x;
    const int stride = gridDim.x * blockDim.x;
    for (; i < n4; i += stride) {
        float4 v = in[i];
        uint2 o;
        o.x = pack2(v.x, v.y);
        o.y = pack2(v.z, v.w);
        out[i] = o;
    }
}

// ---------------------------------------------------------------------------
// Soft top-k mask: one warp per row of 64 z values.  Exact 16th-largest |z|
// (duplicate-counting) via 16 max-extractions; emit z_sparse as fp16.
// ---------------------------------------------------------------------------
__global__ void topk_mask_kernel(const float* __restrict__ z,
                                 __half* __restrict__ zsh, int M)
{
    const int row  = blockIdx.x * 8 + (threadIdx.x >> 5);
    const int lane = threadIdx.x & 31;
    if (row >= M) return;

    float z0 = z[row * R_C + lane];
    float z1 = z[row * R_C + lane + 32];
    float v0 = fabsf(z0), v1 = fabsf(z1);
    bool a0 = true, a1 = true;
    float thr = 0.0f;

#pragma unroll 1
    for (int it = 0; it < KSEL_C; it++) {
        float m = fmaxf(a0 ? v0 : -1.0f, a1 ? v1 : -1.0f);
#pragma unroll
        for (int off = 16; off; off >>= 1)
            m = fmaxf(m, __shfl_xor_sync(0xffffffffu, m, off));
        thr = m;
        unsigned b = __ballot_sync(0xffffffffu, a0 && v0 == m);
        if (b) {
            if (lane == (__ffs(b) - 1)) a0 = false;
        } else {
            unsigned b2 = __ballot_sync(0xffffffffu, a1 && v1 == m);
            if (lane == (__ffs(b2) - 1)) a1 = false;
        }
    }

    const float inv_t = 1.0f / TEMP_C;
    float m0 = 1.0f / (1.0f + expf(-(v0 - thr) * inv_t));
    float m1 = 1.0f / (1.0f + expf(-(v1 - thr) * inv_t));
    zsh[row * R_C + lane]      = __float2half_rn(z0 * m0);
    zsh[row * R_C + lane + 32] = __float2half_rn(z1 * m1);
}

// ---------------------------------------------------------------------------
// Launch
// ---------------------------------------------------------------------------
extern "C" void kernel_launch(void* const* d_in, const int* in_sizes, int n_in,
                              void* d_out, int out_size)
{
    const float* x    = (const float*)d_in[0];   // [M][4096]
    const float* Amat = (const float*)d_in[1];   // [64][4096]
    const float* Bmat = (const float*)d_in[2];   // [4096][64]
    const float* Wmat = (const float*)d_in[3];   // [4096][4096]
    const float* bias = (const float*)d_in[4];   // [4096]
    float* out = (float*)d_out;

    const int M = in_sizes[0] / D_IN_C;          // 8192
    const int N = in_sizes[4];                   // 4096

    uint32_t *xh, *wh, *ah, *bh, *zsh;
    float* zptr;
    cudaGetSymbolAddress((void**)&xh,   g_xh);
    cudaGetSymbolAddress((void**)&wh,   g_wh);
    cudaGetSymbolAddress((void**)&ah,   g_ah);
    cudaGetSymbolAddress((void**)&bh,   g_bh);
    cudaGetSymbolAddress((void**)&zsh,  g_zsh);
    cudaGetSymbolAddress((void**)&zptr, g_z);

    // 0) pre-convert operands to fp16 pairs
    cvt_f16_kernel<<<1024, 256>>>((const float4*)x,    (uint2*)xh, M * D_IN_C / 4);
    cvt_f16_kernel<<<1024, 256>>>((const float4*)Wmat, (uint2*)wh, N * D_IN_C / 4);
    cvt_f16_kernel<<<256,  256>>>((const float4*)Amat, (uint2*)ah, R_C * D_IN_C / 4);
    cvt_f16_kernel<<<256,  256>>>((const float4*)Bmat, (uint2*)bh, N * R_C / 4);

    constexpr int SMEM_MAIN = 2 * (128 + 128) * PITCH * 4;  // 73728 B
    constexpr int SMEM_Z    = 2 * (64 + 64)   * PITCH * 4;  // 36864 B
    cudaFuncSetAttribute(gemm_f16<128, 128, true,  true>,
                         cudaFuncAttributeMaxDynamicSharedMemorySize, SMEM_MAIN);
    cudaFuncSetAttribute(gemm_f16<64,  64,  false, false>,
                         cudaFuncAttributeMaxDynamicSharedMemorySize, SMEM_Z);

    // 1) z = x @ A^T   (M x 64, K = 4096) — BM=64 for 128-CTA occupancy
    {
        dim3 grid(1, M / 64);
        gemm_f16<64, 64, false, false><<<grid, 128, SMEM_Z>>>(
            xh, D_IN_P, ah, D_IN_P,
            nullptr, nullptr, nullptr,
            zptr, R_C,
            D_IN_C / 64, D_IN_C / 64);
    }

    // 2) soft top-k mask -> z_sparse (fp16)
    topk_mask_kernel<<<M / 8, 256>>>(zptr, (__half*)zsh, M);

    // 3) out = x @ W^T + bias + z_sparse @ B^T   (LoRA = one extra K-tile)
    {
        dim3 grid(N / 128, M / 128);
        gemm_f16<128, 128, true, true><<<grid, 128, SMEM_MAIN>>>(
            xh, D_IN_P, wh, D_IN_P,
            zsh, bh, bias,
            out, N,
            D_IN_C / 64, D_IN_C / 64 + 1);
    }
}